// round 16
// baseline (speedup 1.0000x reference)
#include <cuda_runtime.h>
#include <cuda_bf16.h>
#include <cuda_fp16.h>

// P1 FEM evaluation on a structured 17x17 grid over [0,1]^2.
// Direct cell lookup replaces the reference's 512-triangle scan.
//
// DECISION logic is exact fp32 and bitwise-faithful to the JAX reference
// (validated R4-R15):
//  - x*16 is an exact exponent shift; dx, dy, e = dy-dx are EXACT in fp32.
//  - Reference's 6 triangle conditions collapse to: upper wins iff e > -TOL;
//    algebraic fold val = w00 + b*dx + c*dy - max(e,0)*g with
//    b=w10-w00, c=w11-w10, g=w00+w11-w01-w10 (tie band error <= 1e-10*|g|).
//  - Interior grid-line points output 0 (`dead`); x==0 / y==0 edges survive.
//  - fp16 coefficient table (R14) + magic-number floor / bitfield cell index
//    (R15): rel_err 5.038e-4 deterministic, threshold 1e-3.
//
// R16 change (single variable): the per-point table gather was written as
// two adjacent __half2 (4-byte) loads; ptxas may or may not merge them.
// Force ONE LDS.64 by typing the table as uint2[256] and loading a single
// uint2 per point (8-byte aligned), unpacking half2s from register words.
// Config frozen at R15 (thin 4-pt threads, 2048x256, 8 blocks/SM).

__device__ __forceinline__ float add_rm(float a, float b) {
    float r;
    asm("add.rm.f32 %0, %1, %2;" : "=f"(r) : "f"(a), "f"(b));
    return r;
}

__device__ __forceinline__ float eval_point(float X, float Y,
                                            const uint2* __restrict__ tab) {
    const float MAGIC = 8388608.0f;    // 2^23
    float ux = X * 16.0f;              // exact (power-of-2 scale)
    float uy = Y * 16.0f;

    float tx = add_rm(ux, MAGIC);      // == 2^23 + floor(ux), exact
    float ty = add_rm(uy, MAGIC);
    float fx = tx - MAGIC;             // floor(ux), exact
    float fy = ty - MAGIC;

    float dx = ux - fx;                // exact
    float dy = uy - fy;                // exact
    float e  = dy - dx;                // exact

    // Interior grid line -> reference's strict bbox test fails everywhere.
    bool dead = ((dx == 0.0f) && (ux != 0.0f)) || ((dy == 0.0f) && (uy != 0.0f));

    // cell = i*16 + j from the mantissa bits of tx/ty (i,j in [0,15]).
    unsigned cell = ((__float_as_uint(tx) << 4) | __float_as_uint(ty)) & 0xFFu;

    // ONE LDS.64: .x = half2(w00,b), .y = half2(c,g)
    uint2 packed = tab[cell];
    float2 wb = __half22float2(*reinterpret_cast<const __half2*>(&packed.x));
    float2 cg = __half22float2(*reinterpret_cast<const __half2*>(&packed.y));

    float emax = fmaxf(e, 0.0f);
    float val  = fmaf(wb.y, dx, fmaf(cg.x, dy, wb.x));
    val = fmaf(-emax, cg.y, val);

    return dead ? 0.0f : val;
}

__global__ void __launch_bounds__(256, 8)
p1_eval_kernel(const float4* __restrict__ x4,
               const float*  __restrict__ w,
               float4*       __restrict__ out4) {
    // Per-cell fold coefficients, fp16, one 8-byte entry per cell:
    // word0 = half2(w00, b=w10-w00), word1 = half2(c=w11-w10, g=w00+w11-w01-w10).
    __shared__ uint2 tab[256];
    {
        int t = threadIdx.x;           // cell = i*16 + j
        int v = (t >> 4) * 17 + (t & 15);
        float w00 = w[v], w01 = w[v + 1], w10 = w[v + 17], w11 = w[v + 18];
        __half2 h01 = __floats2half2_rn(w00, w10 - w00);
        __half2 h23 = __floats2half2_rn(w11 - w10, (w00 + w11) - (w01 + w10));
        tab[t] = make_uint2(*reinterpret_cast<unsigned*>(&h01),
                            *reinterpret_cast<unsigned*>(&h23));
    }
    __syncthreads();

    // Thin thread: 4 points = 2 input float4 (front-batched), 1 output float4.
    int o = blockIdx.x * 256 + threadIdx.x;    // output float4 index

    float4 a0 = x4[2 * o];
    float4 a1 = x4[2 * o + 1];

    float4 r;
    r.x = eval_point(a0.x, a0.y, tab);
    r.y = eval_point(a0.z, a0.w, tab);
    r.z = eval_point(a1.x, a1.y, tab);
    r.w = eval_point(a1.z, a1.w, tab);

    out4[o] = r;
}

extern "C" void kernel_launch(void* const* d_in, const int* in_sizes, int n_in,
                              void* d_out, int out_size) {
    // Identify inputs by element count: x = largest (4,194,304 floats),
    // weight = 289 floats.
    const float* x = nullptr;
    const float* w = nullptr;
    int max_sz = -1;
    for (int k = 0; k < n_in; k++) {
        if (in_sizes[k] == 289) w = (const float*)d_in[k];
        if (in_sizes[k] > max_sz) { max_sz = in_sizes[k]; x = (const float*)d_in[k]; }
    }

    // 2,097,152 points -> 524,288 output float4 -> 2048 blocks x 256 threads.
    p1_eval_kernel<<<2048, 256>>>((const float4*)x, w, (float4*)d_out);
}

// round 17
// speedup vs baseline: 1.0964x; 1.0964x over previous
#include <cuda_runtime.h>
#include <cuda_bf16.h>
#include <cuda_fp16.h>

// P1 FEM evaluation on a structured 17x17 grid over [0,1]^2.
// Direct cell lookup replaces the reference's 512-triangle scan.
//
// DECISION logic is exact fp32 and bitwise-faithful to the JAX reference
// (validated R4-R16):
//  - x*16 is an exact exponent shift; dx, dy, e = dy-dx are EXACT in fp32.
//  - Reference's 6 triangle conditions collapse to: upper wins iff e > -TOL;
//    algebraic fold val = w00 + b*dx + c*dy - max(e,0)*g with
//    b=w10-w00, c=w11-w10, g=w00+w11-w01-w10 (tie band error <= 1e-10*|g|).
//  - Interior grid-line points output 0 (`dead`); x==0 / y==0 edges survive.
//  - fp16 coefficient table (R14), magic-number floor + bitfield cell index
//    (R15), forced LDS.64 gather (R16): rel_err 5.038e-4 deterministic,
//    threshold 1e-3.
//
// R17 change (merge best-measured shape with best-measured eval):
//  - 8 points/thread, 4 front-batched LDG.128 (MLP=4, the R8 property),
//    results stored per half to cap live ranges
//  - 1024 blocks <= 1184 resident (8/SM) -> TRUE single wave AND half the
//    table-fill prologues (1024 vs 2048 block prologues)
//  - eval unchanged from R16 (single-variable-ish: shape only)

__device__ __forceinline__ float add_rm(float a, float b) {
    float r;
    asm("add.rm.f32 %0, %1, %2;" : "=f"(r) : "f"(a), "f"(b));
    return r;
}

__device__ __forceinline__ float eval_point(float X, float Y,
                                            const uint2* __restrict__ tab) {
    const float MAGIC = 8388608.0f;    // 2^23
    float ux = X * 16.0f;              // exact (power-of-2 scale)
    float uy = Y * 16.0f;

    float tx = add_rm(ux, MAGIC);      // == 2^23 + floor(ux), exact
    float ty = add_rm(uy, MAGIC);
    float fx = tx - MAGIC;             // floor(ux), exact
    float fy = ty - MAGIC;

    float dx = ux - fx;                // exact
    float dy = uy - fy;                // exact
    float e  = dy - dx;                // exact

    // Interior grid line -> reference's strict bbox test fails everywhere.
    bool dead = ((dx == 0.0f) && (ux != 0.0f)) || ((dy == 0.0f) && (uy != 0.0f));

    // cell = i*16 + j from the mantissa bits of tx/ty (i,j in [0,15]).
    unsigned cell = ((__float_as_uint(tx) << 4) | __float_as_uint(ty)) & 0xFFu;

    // ONE LDS.64: .x = half2(w00,b), .y = half2(c,g)
    uint2 packed = tab[cell];
    float2 wb = __half22float2(*reinterpret_cast<const __half2*>(&packed.x));
    float2 cg = __half22float2(*reinterpret_cast<const __half2*>(&packed.y));

    float emax = fmaxf(e, 0.0f);
    float val  = fmaf(wb.y, dx, fmaf(cg.x, dy, wb.x));
    val = fmaf(-emax, cg.y, val);

    return dead ? 0.0f : val;
}

__global__ void __launch_bounds__(256, 8)
p1_eval_kernel(const float4* __restrict__ x4,
               const float*  __restrict__ w,
               float4*       __restrict__ out4) {
    // Per-cell fold coefficients, fp16, one 8-byte entry per cell:
    // word0 = half2(w00, b=w10-w00), word1 = half2(c=w11-w10, g=w00+w11-w01-w10).
    __shared__ uint2 tab[256];
    {
        int t = threadIdx.x;           // cell = i*16 + j
        int v = (t >> 4) * 17 + (t & 15);
        float w00 = w[v], w01 = w[v + 1], w10 = w[v + 17], w11 = w[v + 18];
        __half2 h01 = __floats2half2_rn(w00, w10 - w00);
        __half2 h23 = __floats2half2_rn(w11 - w10, (w00 + w11) - (w01 + w10));
        tab[t] = make_uint2(*reinterpret_cast<unsigned*>(&h01),
                            *reinterpret_cast<unsigned*>(&h23));
    }
    __syncthreads();

    // Each thread: 8 points = 4 input float4 (front-batched), 2 output float4.
    int o0 = blockIdx.x * 512 + threadIdx.x;   // output float4 index
    int o1 = o0 + 256;

    float4 a0 = x4[2 * o0];
    float4 a1 = x4[2 * o0 + 1];
    float4 b0 = x4[2 * o1];
    float4 b1 = x4[2 * o1 + 1];

    float4 r0;
    r0.x = eval_point(a0.x, a0.y, tab);
    r0.y = eval_point(a0.z, a0.w, tab);
    r0.z = eval_point(a1.x, a1.y, tab);
    r0.w = eval_point(a1.z, a1.w, tab);
    out4[o0] = r0;

    float4 r1;
    r1.x = eval_point(b0.x, b0.y, tab);
    r1.y = eval_point(b0.z, b0.w, tab);
    r1.z = eval_point(b1.x, b1.y, tab);
    r1.w = eval_point(b1.z, b1.w, tab);
    out4[o1] = r1;
}

extern "C" void kernel_launch(void* const* d_in, const int* in_sizes, int n_in,
                              void* d_out, int out_size) {
    // Identify inputs by element count: x = largest (4,194,304 floats),
    // weight = 289 floats.
    const float* x = nullptr;
    const float* w = nullptr;
    int max_sz = -1;
    for (int k = 0; k < n_in; k++) {
        if (in_sizes[k] == 289) w = (const float*)d_in[k];
        if (in_sizes[k] > max_sz) { max_sz = in_sizes[k]; x = (const float*)d_in[k]; }
    }

    // 2,097,152 points -> 524,288 output float4 -> 1024 blocks x 256 threads x 2.
    p1_eval_kernel<<<1024, 256>>>((const float4*)x, w, (float4*)d_out);
}